// round 12
// baseline (speedup 1.0000x reference)
#include <cuda_runtime.h>
#include <cuda_fp16.h>
#include <math.h>
#include <stdint.h>

// ---------------------------------------------------------------------------
// Beam search generator: B=16, BEAM=4, MAX_LEN=16, VOCAB=32000, D=512, S=128
// R12: fp16x2 mma.sync GEMM with last-block rz reduction; score kernel with
// warp-shuffle top-8 + fused book/prep tail (2 kernels per step).
// ---------------------------------------------------------------------------

#define B_      16
#define BEAM_   4
#define MAXLEN_ 16
#define V_      32000
#define D_      512
#define S_      128
#define NR_     64
#define NEG_INF_PEN 1e9f

#define WSZ     (V_ * D_)
#define XSZ     (NR_ * D_)
#define NBLK    250                   // gemm grid

// ------------------------------ device state --------------------------------
static __device__ __align__(16) float g_pooled[B_ * D_];
static __device__ __align__(16) __half g_Wsp16[2 * WSZ];        // W splits, [s][n][k]
static __device__ __align__(16) __half g_xsp16[2 * XSZ];        // x splits, [s][r][k]
static __device__ __align__(16) float g_logits[(size_t)NR_ * V_];
static __device__ float g_alive_lp[B_ * BEAM_];
static __device__ int   g_alive_seq[B_ * BEAM_ * MAXLEN_];
static __device__ float g_fin_scores[B_ * BEAM_];
static __device__ int   g_fin_seq[B_ * BEAM_ * MAXLEN_];
static __device__ int   g_fin_flags[B_ * BEAM_];
static __device__ int   g_batch_fin[B_];
static __device__ __align__(16) float2 g_pms2[NR_ * 256];       // per-(row,block) LSE partials
static __device__ __align__(16) float2 g_rmz[NR_];              // per-row (max, logZ)
static __device__ unsigned long long g_cand[NR_ * 32];          // 4 quarters x 8 keys
static __device__ unsigned g_cnt_gemm = 0;
static __device__ unsigned g_cnt_sc = 0;

// ------------------------------ generic helpers ------------------------------
__device__ __forceinline__ unsigned int ford(float f) {
    unsigned int u = __float_as_uint(f);
    return (u & 0x80000000u) ? ~u : (u | 0x80000000u);
}
__device__ __forceinline__ float finv(unsigned int u) {
    return __uint_as_float((u & 0x80000000u) ? (u ^ 0x80000000u) : ~u);
}
__device__ __forceinline__ unsigned long long umax64(unsigned long long a, unsigned long long b) {
    return a > b ? a : b;
}
// exp(u) for u in [-0.25, 0] on the FMA pipe; rel err < 2e-8. MUFU fallback else.
__device__ __forceinline__ float pexp(float u) {
    if (u < -0.25f) return __expf(u);
    float p = fmaf(u, 1.0f / 720.0f, 1.0f / 120.0f);
    p = fmaf(u, p, 1.0f / 24.0f);
    p = fmaf(u, p, 1.0f / 6.0f);
    p = fmaf(u, p, 0.5f);
    p = fmaf(u, p, 1.0f);
    p = fmaf(u, p, 1.0f);
    return p;
}
// online logsumexp pair merge (symmetric)
__device__ __forceinline__ void lse_mrg(float& m1, float& s1, float m2, float s2) {
    if (m2 > m1) { s1 = s1 * pexp(m1 - m2) + s2; m1 = m2; }
    else         { s1 += s2 * pexp(m2 - m1); }
}

// ------------------------------ PTX helpers (sm_80 baseline) -----------------
__device__ __forceinline__ uint32_t smem_u32(const void* p) {
    uint32_t a;
    asm("{ .reg .u64 t; cvta.to.shared.u64 t, %1; cvt.u32.u64 %0, t; }" : "=r"(a) : "l"(p));
    return a;
}
__device__ __forceinline__ void cp16(uint32_t dst, const void* src) {
    asm volatile("{ .reg .u64 g; cvta.to.global.u64 g, %1;\n\t"
                 "cp.async.cg.shared.global [%0], [g], 16; }"
                 :: "r"(dst), "l"(src) : "memory");
}
#define CP_COMMIT() asm volatile("cp.async.commit_group;" ::: "memory")
#define CP_WAIT1()  asm volatile("cp.async.wait_group 1;" ::: "memory")
#define CP_WAIT0()  asm volatile("cp.async.wait_group 0;" ::: "memory")

#define LDMX4(r0, r1, r2, r3, addr) \
    asm volatile("ldmatrix.sync.aligned.m8n8.x4.shared.b16 {%0,%1,%2,%3}, [%4];" \
                 : "=r"(r0), "=r"(r1), "=r"(r2), "=r"(r3) : "r"(addr))

#define MMAF16(d, a, b0r, b1r) \
    asm volatile("mma.sync.aligned.m16n8k16.row.col.f32.f16.f16.f32 " \
                 "{%0,%1,%2,%3}, {%4,%5,%6,%7}, {%8,%9}, {%0,%1,%2,%3};" \
                 : "+f"((d)[0]), "+f"((d)[1]), "+f"((d)[2]), "+f"((d)[3]) \
                 : "r"((a)[0]), "r"((a)[1]), "r"((a)[2]), "r"((a)[3]), \
                   "r"(b0r), "r"(b1r))

// SW64 swizzle for 64-byte rows: r = row, f = 16B-granule index (0..3)
__device__ __forceinline__ uint32_t swz64(int r, int f) {
    return (uint32_t)(r * 64 + ((f * 16) ^ ((r & 6) * 8)));
}

// ------------------------------ fused setup: wprep + init + pooling ----------
__global__ void __launch_bounds__(256) k_setup(const int* __restrict__ src,
                                               const float* __restrict__ Esrc,
                                               const float* __restrict__ W) {
    int tid = threadIdx.x;
    if (blockIdx.x < 4000) {           // W split (fp16x2) + transpose
        int ktile = blockIdx.x & 7;
        int ntile = blockIdx.x >> 3;
        int k0 = ktile * 64, n0 = ntile * 64;
        __shared__ float tile[64][65];
        for (int i = tid; i < 4096; i += 256) {
            int kk = i >> 6, nn = i & 63;
            tile[kk][nn] = W[(size_t)(k0 + kk) * V_ + n0 + nn];
        }
        __syncthreads();
        for (int i = tid; i < 4096; i += 256) {
            int nn = i >> 6, kk = i & 63;
            float v = tile[kk][nn];
            __half h0 = __float2half_rn(v);
            float r1 = v - __half2float(h0);
            __half h1 = __float2half_rn(r1);
            size_t o = (size_t)(n0 + nn) * D_ + k0 + kk;
            g_Wsp16[o] = h0;
            g_Wsp16[WSZ + o] = h1;
        }
        return;
    }
    int blk = blockIdx.x - 4000;
    if (blk == 16) {                   // state init
        for (int i = tid; i < 1024; i += 256) {
            g_alive_seq[i] = ((i & (MAXLEN_ - 1)) == 0) ? 1 : 0;
            g_fin_seq[i] = 0;
        }
        if (tid < B_ * BEAM_) {
            g_alive_lp[tid]   = ((tid & (BEAM_ - 1)) == 0) ? 0.0f : -INFINITY;
            g_fin_scores[tid] = -NEG_INF_PEN;
            g_fin_flags[tid]  = 0;
        }
        if (tid < B_) g_batch_fin[tid] = 0;
        return;
    }
    int b = blk;                       // encoder pooling for batch b
    __shared__ int toks[S_];
    if (tid < S_) toks[tid] = src[b * S_ + tid];
    __syncthreads();
    float cnt = 0.0f;
    for (int s = 0; s < S_; s++) cnt += (toks[s] != 0) ? 1.0f : 0.0f;
    float denom = fmaxf(cnt, 1.0f);
    for (int d = tid; d < D_; d += blockDim.x) {
        float acc = 0.0f;
        for (int s = 0; s < S_; s++) {
            int tk = toks[s];
            if (tk != 0) acc += Esrc[(size_t)tk * D_ + d];
        }
        g_pooled[b * D_ + d] = __fdiv_rn(acc, denom);
    }
}

// ------------------------------ x prep + fp16x2 split (t=0 only) -------------
__global__ void __launch_bounds__(512) k_prep(const float* __restrict__ Etgt, int t) {
    int r = blockIdx.x;
    int b = r >> 2;
    int tok = g_alive_seq[r * MAXLEN_ + t];
    int k = threadIdx.x;
    float v = Etgt[(size_t)tok * D_ + k] + g_pooled[b * D_ + k];
    __half h0 = __float2half_rn(v);
    float r1 = v - __half2float(h0);
    __half h1 = __float2half_rn(r1);
    int o = r * D_ + k;
    g_xsp16[o] = h0;
    g_xsp16[XSZ + o] = h1;
}

// ------------------------------ tensor-core GEMM + LSE + rz tail -------------
#define NCHUNK  16
#define STAGE_B 24576

__global__ void __launch_bounds__(256, 2) k_gemm(const float* __restrict__ bias) {
    extern __shared__ __align__(128) char smem[];
    __shared__ unsigned s_tk;
    const uint32_t base = smem_u32(smem);
    const int tid  = threadIdx.x;
    const int lane = tid & 31;
    const int wid  = tid >> 5;
    const int warp_m = wid >> 2;
    const int warp_n = wid & 3;
    const int nb = blockIdx.x * 128;

    static const int AI[3] = {0, 0, 1};
    static const int BI[3] = {0, 1, 0};

    float acc[2][4][4];
#pragma unroll
    for (int i = 0; i < 2; i++)
#pragma unroll
        for (int j = 0; j < 4; j++)
#pragma unroll
            for (int q = 0; q < 4; q++) acc[i][j][q] = 0.0f;

    const int arow = lane & 15;
    const int asel = lane >> 4;
    const int brow = (lane & 7) + 8 * ((lane >> 4) & 1);
    const int bsel = (lane >> 3) & 1;

    auto issue = [&](int c, int st) {
        const int k0 = c * 32;
        uint32_t sb = base + st * STAGE_B;
#pragma unroll
        for (int i = 0; i < 6; i++) {
            int seg = tid + i * 256;
            if (seg < 512) {
                int s = seg >> 8, rem = seg & 255;
                int r = rem >> 2, f = rem & 3;
                cp16(sb + (uint32_t)(s * 4096) + swz64(r, f),
                     g_xsp16 + s * XSZ + r * D_ + k0 + f * 8);
            } else {
                int q = seg - 512;
                int s = q >> 9, rem = q & 511;
                int n = rem >> 2, f = rem & 3;
                cp16(sb + 8192u + (uint32_t)(s * 8192) + swz64(n, f),
                     g_Wsp16 + (size_t)s * WSZ + (size_t)(nb + n) * D_ + k0 + f * 8);
            }
        }
    };

    issue(0, 0); CP_COMMIT();
    issue(1, 1); CP_COMMIT();

    for (int c = 0; c < NCHUNK; c++) {
        const int st = c % 3;
        CP_WAIT1();
        __syncthreads();
        if (c + 2 < NCHUNK) issue(c + 2, (c + 2) % 3);
        CP_COMMIT();

        const uint32_t As0 = base + st * STAGE_B;
        const uint32_t Bs0 = As0 + 8192u;
#pragma unroll
        for (int p = 0; p < 3; p++) {
            const uint32_t As = As0 + (uint32_t)(AI[p] * 4096);
            const uint32_t Bs = Bs0 + (uint32_t)(BI[p] * 8192);
#pragma unroll
            for (int ks = 0; ks < 2; ks++) {
                uint32_t af[2][4], bf[2][4];
#pragma unroll
                for (int i = 0; i < 2; i++) {
                    int r = warp_m * 32 + i * 16 + arow;
                    LDMX4(af[i][0], af[i][1], af[i][2], af[i][3],
                          As + swz64(r, ks * 2 + asel));
                }
#pragma unroll
                for (int jp = 0; jp < 2; jp++) {
                    int n = warp_n * 32 + jp * 16 + brow;
                    LDMX4(bf[jp][0], bf[jp][1], bf[jp][2], bf[jp][3],
                          Bs + swz64(n, ks * 2 + bsel));
                }
#pragma unroll
                for (int i = 0; i < 2; i++) {
#pragma unroll
                    for (int jn = 0; jn < 4; jn++) {
                        MMAF16(acc[i][jn], af[i], bf[jn >> 1][(jn & 1) * 2],
                               bf[jn >> 1][(jn & 1) * 2 + 1]);
                    }
                }
            }
        }
    }

    // ---- epilogue: store logits + per-(row, block) logsumexp partials ----
    CP_WAIT0();
    __syncthreads();
    float2* sl = reinterpret_cast<float2*>(smem);   // [64][4]

#pragma unroll
    for (int i = 0; i < 2; i++) {
        float lv0[8], lv1[8];
        int row0 = warp_m * 32 + i * 16 + (lane >> 2);
#pragma unroll
        for (int jn = 0; jn < 4; jn++) {
            int col = nb + warp_n * 32 + jn * 8 + (lane & 3) * 2;
            float2 bz = *reinterpret_cast<const float2*>(bias + col);
            float2 o0 = make_float2(acc[i][jn][0] + bz.x, acc[i][jn][1] + bz.y);
            float2 o1 = make_float2(acc[i][jn][2] + bz.x, acc[i][jn][3] + bz.y);
            *reinterpret_cast<float2*>(g_logits + (size_t)row0 * V_ + col) = o0;
            *reinterpret_cast<float2*>(g_logits + (size_t)(row0 + 8) * V_ + col) = o1;
            lv0[jn * 2] = o0.x; lv0[jn * 2 + 1] = o0.y;
            lv1[jn * 2] = o1.x; lv1[jn * 2 + 1] = o1.y;
        }
#pragma unroll
        for (int h = 0; h < 2; h++) {
            const float* lv = (h == 0) ? lv0 : lv1;
            float m = lv[0];
#pragma unroll
            for (int j = 1; j < 8; j++) m = fmaxf(m, lv[j]);
            float s = 0.0f;
#pragma unroll
            for (int j = 0; j < 8; j++) s += pexp(lv[j] - m);
#pragma unroll
            for (int off = 1; off <= 2; off <<= 1) {
                float om = __shfl_xor_sync(0xFFFFFFFFu, m, off);
                float os = __shfl_xor_sync(0xFFFFFFFFu, s, off);
                lse_mrg(m, s, om, os);
            }
            if ((lane & 3) == 0) {
                int rl = warp_m * 32 + i * 16 + h * 8 + (lane >> 2);
                sl[rl * 4 + warp_n] = make_float2(m, s);
            }
        }
    }
    __syncthreads();
    if (tid < 64) {
        float m = sl[tid * 4].x, s = sl[tid * 4].y;
#pragma unroll
        for (int j = 1; j < 4; j++)
            lse_mrg(m, s, sl[tid * 4 + j].x, sl[tid * 4 + j].y);
        g_pms2[tid * 256 + blockIdx.x] = make_float2(m, s);
    }

    // ---- last-block tail: reduce partials -> per-row (rm, rz) ----
    __threadfence();
    __syncthreads();
    if (tid == 0) s_tk = atomicAdd(&g_cnt_gemm, 1u);
    __syncthreads();
    if (s_tk == NBLK - 1) {
        for (int row = wid * 8; row < wid * 8 + 8; row++) {
            float m = -INFINITY, s = 0.0f;
            for (int i = lane; i < NBLK; i += 32) {
                float2 p = g_pms2[row * 256 + i];
                lse_mrg(m, s, p.x, p.y);
            }
#pragma unroll
            for (int off = 16; off > 0; off >>= 1) {
                float om = __shfl_xor_sync(0xFFFFFFFFu, m, off);
                float os = __shfl_xor_sync(0xFFFFFFFFu, s, off);
                lse_mrg(m, s, om, os);
            }
            if (lane == 0) g_rmz[row] = make_float2(m, logf(s));
        }
        __syncthreads();
        if (tid == 0) g_cnt_gemm = 0;
    }
}

// ------------------------------ score + fused book/prep tail -----------------
// grid 256 = 4 blocks/row. Scan quarter for top-8 under the exact key, warp-
// shuffle selection (1 barrier). Last block (ticket) runs beam bookkeeping
// (8 warps x 2 batches) and preps x splits for step t+1.
__global__ void __launch_bounds__(256) k_score(const float* __restrict__ Etgt, int t) {
    const int blk = blockIdx.x;
    const int r = blk >> 2, q = blk & 3;
    const int tid = threadIdx.x;
    const int lane = tid & 31;
    const int wid = tid >> 5;
    const float lpen = (float)(t + 1);

    __shared__ unsigned long long wk[8][8];
    __shared__ unsigned s_tk;
    __shared__ int s_tok[NR_];

    {
        float2 mz = g_rmz[r];
        const float rm = mz.x, rz = mz.y;
        const float al = g_alive_lp[r];
        const unsigned int idxBase = (unsigned int)((r & 3) * V_ + q * 8000);

        const float4* lrow = reinterpret_cast<const float4*>(g_logits + (size_t)r * V_ + q * 8000);
        unsigned long long loc[8];
#pragma unroll
        for (int i = 0; i < 8; i++) loc[i] = 0ull;

        for (int i = tid; i < 2000; i += 256) {
            float4 x = lrow[i];
            float xs[4] = {x.x, x.y, x.z, x.w};
#pragma unroll
            for (int c = 0; c < 4; c++) {
                float lp = (xs[c] - rm) - rz;
                float sc = __fdiv_rn(al + lp, lpen);
                unsigned int idx = idxBase + (unsigned int)(i * 4 + c);
                unsigned long long key = ((unsigned long long)ford(sc) << 32)
                                       | (unsigned long long)(0xFFFFFFFFu - idx);
                if (key > loc[7]) {
                    loc[7] = key;
#pragma unroll
                    for (int j = 7; j > 0; j--) {
                        if (loc[j] > loc[j - 1]) {
                            unsigned long long tmp = loc[j]; loc[j] = loc[j - 1]; loc[j - 1] = tmp;
                        }
                    }
                }
            }
        }

        // per-warp top-8 (loc sorted descending; extract + remove)
#pragma unroll
        for (int sel = 0; sel < 8; sel++) {
            unsigned long long mx = loc[0];
#pragma unroll
            for (int off = 16; off > 0; off >>= 1)
                mx = umax64(mx, __shfl_xor_sync(0xFFFFFFFFu, mx, off));
            if (loc[0] == mx) {
#pragma unroll
                for (int j = 0; j < 7; j++) loc[j] = loc[j + 1];
                loc[7] = 0ull;
            }
            if (lane == 0) wk[wid][sel] = mx;
        }
        __syncthreads();
        if (wid == 0) {
            const unsigned long long* fw = &wk[0][0];
            unsigned long long a = fw[lane], b = fw[lane + 32];
#pragma unroll
            for (int sel = 0; sel < 8; sel++) {
                unsigned long long mm = umax64(a, b);
#pragma unroll
                for (int off = 16; off > 0; off >>= 1)
                    mm = umax64(mm, __shfl_xor_sync(0xFFFFFFFFu, mm, off));
                if (a == mm) a = 0ull;
                else if (b == mm) b = 0ull;
                if (lane == 0) g_cand[r * 32 + q * 8 + sel] = mm;
            }
        }
    }

    // ---- ticket: last block runs book + prep ----
    __threadfence();
    __syncthreads();
    if (tid == 0) s_tk = atomicAdd(&g_cnt_sc, 1u);
    __syncthreads();
    if (s_tk != 255) return;

    for (int b = wid * 2; b <= wid * 2 + 1; b++) {
        unsigned long long k4[4];
#pragma unroll
        for (int j = 0; j < 4; j++) k4[j] = g_cand[b * 128 + lane * 4 + j];

        float sc[8]; int id[8];
#pragma unroll
        for (int sel = 0; sel < 8; sel++) {
            unsigned long long mx = umax64(umax64(k4[0], k4[1]), umax64(k4[2], k4[3]));
#pragma unroll
            for (int off = 16; off > 0; off >>= 1)
                mx = umax64(mx, __shfl_xor_sync(0xFFFFFFFFu, mx, off));
            sc[sel] = finv((unsigned int)(mx >> 32));
            id[sel] = (int)(0xFFFFFFFFu - (unsigned int)mx);
#pragma unroll
            for (int j = 0; j < 4; j++)
                if (k4[j] == mx) k4[j] = 0ull;
        }

        int tok[8], bix[8], fin[8]; float tlp[8];
#pragma unroll
        for (int j = 0; j < 8; j++) {
            tok[j] = id[j] % V_;
            bix[j] = (t == 0) ? (j & 3) : (id[j] / V_);
            fin[j] = (tok[j] == 2);
            tlp[j] = sc[j] * lpen;
        }

        float curr[8];
#pragma unroll
        for (int j = 0; j < 8; j++) curr[j] = sc[j] + (fin[j] ? -NEG_INF_PEN : 0.0f);
        int aidx[4];
        {
            unsigned usedm = 0;
#pragma unroll
            for (int sel = 0; sel < 4; sel++) {
                int best = -1; float bv = 0.0f;
#pragma unroll
                for (int j = 0; j < 8; j++)
                    if (!((usedm >> j) & 1) && (best < 0 || curr[j] > bv)) {
                        best = j; bv = curr[j];
                    }
                usedm |= 1u << best; aidx[sel] = best;
            }
        }

        float bfp = g_batch_fin[b] ? -NEG_INF_PEN : 0.0f;
        float cs[12]; int cfl[12];
#pragma unroll
        for (int k = 0; k < 4; k++) {
            cs[k]  = g_fin_scores[b * BEAM_ + k];
            cfl[k] = g_fin_flags[b * BEAM_ + k];
        }
#pragma unroll
        for (int j = 0; j < 8; j++) {
            cs[4 + j]  = (sc[j] + (fin[j] ? 0.0f : -NEG_INF_PEN)) + bfp;
            cfl[4 + j] = fin[j];
        }
        int fidx[4];
        {
            unsigned usedm = 0;
#pragma unroll
            for (int sel = 0; sel < 4; sel++) {
                int best = -1; float bv = 0.0f;
#pragma unroll
                for (int j = 0; j < 12; j++)
                    if (!((usedm >> j) & 1) && (best < 0 || cs[j] > bv)) {
                        best = j; bv = cs[j];
                    }
                usedm |= 1u << best; fidx[sel] = best;
            }
        }

        if (lane < MAXLEN_) {
            int a_old[4], f_old[4];
#pragma unroll
            for (int k = 0; k < 4; k++) {
                a_old[k] = g_alive_seq[(b * BEAM_ + k) * MAXLEN_ + lane];
                f_old[k] = g_fin_seq[(b * BEAM_ + k) * MAXLEN_ + lane];
            }
            int a_new[4], f_new[4];
#pragma unroll
            for (int k = 0; k < 4; k++) {
                int aj = aidx[k];
                int v = a_old[bix[aj]];
                if (lane == t + 1) v = tok[aj];
                a_new[k] = v;

                int fj = fidx[k];
                int w;
                if (fj < 4) {
                    w = f_old[fj];
                } else {
                    w = a_old[bix[fj - 4]];
                    if (lane == t + 1) w = tok[fj - 4];
                }
                f_new[k] = w;
            }
#pragma unroll
            for (int k = 0; k < 4; k++) {
                g_alive_seq[(b * BEAM_ + k) * MAXLEN_ + lane] = a_new[k];
                g_fin_seq[(b * BEAM_ + k) * MAXLEN_ + lane]   = f_new[k];
            }
        }

        if (lane == 0) {
            float nalp[4], nfsc[4]; int nffl[4];
#pragma unroll
            for (int k = 0; k < 4; k++) {
                nalp[k] = tlp[aidx[k]];
                nfsc[k] = cs[fidx[k]];
                nffl[k] = cfl[fidx[k]];
                g_alive_lp[b * BEAM_ + k]   = nalp[k];
                g_fin_scores[b * BEAM_ + k] = nfsc[k];
                g_fin_flags[b * BEAM_ + k]  = nffl[k];
            }
            float lb = __fdiv_rn(nalp[0], lpen);
            float lf = nfsc[0] * (nffl[0] ? 1.0f : 0.0f);
#pragma unroll
            for (int k = 1; k < 4; k++) lf = fminf(lf, nfsc[k] * (nffl[k] ? 1.0f : 0.0f));
            bool allf = nffl[0] && nffl[1] && nffl[2] && nffl[3];
            lf = lf + (allf ? 0.0f : -NEG_INF_PEN);
            if (lf >= lb) g_batch_fin[b] = 1;
        }
    }
    __syncthreads();

    // ---- prep x splits for step t+1 ----
    if (t + 1 < MAXLEN_ - 1) {
        if (tid < NR_) s_tok[tid] = g_alive_seq[tid * MAXLEN_ + t + 1];
        __syncthreads();
        for (int idx = tid; idx < NR_ * D_; idx += 256) {
            int rr = idx >> 9, k = idx & 511;
            float v = Etgt[(size_t)s_tok[rr] * D_ + k] + g_pooled[(rr >> 2) * D_ + k];
            __half h0 = __float2half_rn(v);
            float r1 = v - __half2float(h0);
            __half h1 = __float2half_rn(r1);
            g_xsp16[idx] = h0;
            g_xsp16[XSZ + idx] = h1;
        }
    }
    __syncthreads();
    if (tid == 0) g_cnt_sc = 0;
}

// ------------------------------ output ---------------------------------------
__global__ void k_out(int* __restrict__ out) {
    int i = threadIdx.x;
    if (i < B_ * MAXLEN_) {
        int b = i / MAXLEN_, l = i % MAXLEN_;
        out[i] = g_fin_seq[(b * BEAM_ + 0) * MAXLEN_ + l];
    }
}

// ------------------------------ launcher -------------------------------------
extern "C" void kernel_launch(void* const* d_in, const int* in_sizes, int n_in,
                              void* d_out, int out_size) {
    (void)in_sizes; (void)n_in; (void)out_size;
    const int*   src  = (const int*)d_in[0];
    const float* Esrc = (const float*)d_in[1];
    const float* Etgt = (const float*)d_in[2];
    const float* W    = (const float*)d_in[3];
    const float* bias = (const float*)d_in[4];

    static int s_attr_done = 0;
    if (!s_attr_done) {
        cudaFuncSetAttribute(k_gemm, cudaFuncAttributeMaxDynamicSharedMemorySize,
                             3 * STAGE_B);
        s_attr_done = 1;
    }

    // launch order: setup(1), prep(2), gemm(3), score(4) <- ncu capture slot
    k_setup<<<4017, 256>>>(src, Esrc, W);
    k_prep<<<NR_, 512>>>(Etgt, 0);

    for (int t = 0; t < MAXLEN_ - 1; t++) {
        k_gemm<<<NBLK, 256, 3 * STAGE_B>>>(bias);
        k_score<<<NR_ * 4, 256>>>(Etgt, t);
    }
    k_out<<<1, 256>>>((int*)d_out);
}

// round 13
// speedup vs baseline: 1.2509x; 1.2509x over previous
#include <cuda_runtime.h>
#include <cuda_fp16.h>
#include <math.h>
#include <stdint.h>

// ---------------------------------------------------------------------------
// Beam search generator: B=16, BEAM=4, MAX_LEN=16, VOCAB=32000, D=512, S=128
// R13: fp16x2 mma.sync GEMM with last-block rz reduction; score kernel with
// warp-shuffle top-8 (no serial tail); separate parallel book + prep kernels.
// ---------------------------------------------------------------------------

#define B_      16
#define BEAM_   4
#define MAXLEN_ 16
#define V_      32000
#define D_      512
#define S_      128
#define NR_     64
#define NEG_INF_PEN 1e9f

#define WSZ     (V_ * D_)
#define XSZ     (NR_ * D_)
#define NBLK    250                   // gemm grid

// ------------------------------ device state --------------------------------
static __device__ __align__(16) float g_pooled[B_ * D_];
static __device__ __align__(16) __half g_Wsp16[2 * WSZ];        // W splits, [s][n][k]
static __device__ __align__(16) __half g_xsp16[2 * XSZ];        // x splits, [s][r][k]
static __device__ __align__(16) float g_logits[(size_t)NR_ * V_];
static __device__ float g_alive_lp[B_ * BEAM_];
static __device__ int   g_alive_seq[B_ * BEAM_ * MAXLEN_];
static __device__ float g_fin_scores[B_ * BEAM_];
static __device__ int   g_fin_seq[B_ * BEAM_ * MAXLEN_];
static __device__ int   g_fin_flags[B_ * BEAM_];
static __device__ int   g_batch_fin[B_];
static __device__ __align__(16) float2 g_pms2[NR_ * 256];       // per-(row,block) LSE partials
static __device__ __align__(16) float2 g_rmz[NR_];              // per-row (max, logZ)
static __device__ unsigned long long g_cand[NR_ * 32];          // 4 quarters x 8 keys
static __device__ unsigned g_cnt_gemm = 0;

// ------------------------------ generic helpers ------------------------------
__device__ __forceinline__ unsigned int ford(float f) {
    unsigned int u = __float_as_uint(f);
    return (u & 0x80000000u) ? ~u : (u | 0x80000000u);
}
__device__ __forceinline__ float finv(unsigned int u) {
    return __uint_as_float((u & 0x80000000u) ? (u ^ 0x80000000u) : ~u);
}
__device__ __forceinline__ unsigned long long umax64(unsigned long long a, unsigned long long b) {
    return a > b ? a : b;
}
// exp(u) for u in [-0.25, 0] on the FMA pipe; rel err < 2e-8. MUFU fallback else.
__device__ __forceinline__ float pexp(float u) {
    if (u < -0.25f) return __expf(u);
    float p = fmaf(u, 1.0f / 720.0f, 1.0f / 120.0f);
    p = fmaf(u, p, 1.0f / 24.0f);
    p = fmaf(u, p, 1.0f / 6.0f);
    p = fmaf(u, p, 0.5f);
    p = fmaf(u, p, 1.0f);
    p = fmaf(u, p, 1.0f);
    return p;
}
// online logsumexp pair merge (symmetric)
__device__ __forceinline__ void lse_mrg(float& m1, float& s1, float m2, float s2) {
    if (m2 > m1) { s1 = s1 * pexp(m1 - m2) + s2; m1 = m2; }
    else         { s1 += s2 * pexp(m2 - m1); }
}

// ------------------------------ PTX helpers (sm_80 baseline) -----------------
__device__ __forceinline__ uint32_t smem_u32(const void* p) {
    uint32_t a;
    asm("{ .reg .u64 t; cvta.to.shared.u64 t, %1; cvt.u32.u64 %0, t; }" : "=r"(a) : "l"(p));
    return a;
}
__device__ __forceinline__ void cp16(uint32_t dst, const void* src) {
    asm volatile("{ .reg .u64 g; cvta.to.global.u64 g, %1;\n\t"
                 "cp.async.cg.shared.global [%0], [g], 16; }"
                 :: "r"(dst), "l"(src) : "memory");
}
#define CP_COMMIT() asm volatile("cp.async.commit_group;" ::: "memory")
#define CP_WAIT1()  asm volatile("cp.async.wait_group 1;" ::: "memory")
#define CP_WAIT0()  asm volatile("cp.async.wait_group 0;" ::: "memory")

#define LDMX4(r0, r1, r2, r3, addr) \
    asm volatile("ldmatrix.sync.aligned.m8n8.x4.shared.b16 {%0,%1,%2,%3}, [%4];" \
                 : "=r"(r0), "=r"(r1), "=r"(r2), "=r"(r3) : "r"(addr))

#define MMAF16(d, a, b0r, b1r) \
    asm volatile("mma.sync.aligned.m16n8k16.row.col.f32.f16.f16.f32 " \
                 "{%0,%1,%2,%3}, {%4,%5,%6,%7}, {%8,%9}, {%0,%1,%2,%3};" \
                 : "+f"((d)[0]), "+f"((d)[1]), "+f"((d)[2]), "+f"((d)[3]) \
                 : "r"((a)[0]), "r"((a)[1]), "r"((a)[2]), "r"((a)[3]), \
                   "r"(b0r), "r"(b1r))

// SW64 swizzle for 64-byte rows: r = row, f = 16B-granule index (0..3)
__device__ __forceinline__ uint32_t swz64(int r, int f) {
    return (uint32_t)(r * 64 + ((f * 16) ^ ((r & 6) * 8)));
}

// ------------------------------ fused setup: wprep + init + pooling ----------
__global__ void __launch_bounds__(256) k_setup(const int* __restrict__ src,
                                               const float* __restrict__ Esrc,
                                               const float* __restrict__ W) {
    int tid = threadIdx.x;
    if (blockIdx.x < 4000) {           // W split (fp16x2) + transpose
        int ktile = blockIdx.x & 7;
        int ntile = blockIdx.x >> 3;
        int k0 = ktile * 64, n0 = ntile * 64;
        __shared__ float tile[64][65];
        for (int i = tid; i < 4096; i += 256) {
            int kk = i >> 6, nn = i & 63;
            tile[kk][nn] = W[(size_t)(k0 + kk) * V_ + n0 + nn];
        }
        __syncthreads();
        for (int i = tid; i < 4096; i += 256) {
            int nn = i >> 6, kk = i & 63;
            float v = tile[kk][nn];
            __half h0 = __float2half_rn(v);
            float r1 = v - __half2float(h0);
            __half h1 = __float2half_rn(r1);
            size_t o = (size_t)(n0 + nn) * D_ + k0 + kk;
            g_Wsp16[o] = h0;
            g_Wsp16[WSZ + o] = h1;
        }
        return;
    }
    int blk = blockIdx.x - 4000;
    if (blk == 16) {                   // state init
        for (int i = tid; i < 1024; i += 256) {
            g_alive_seq[i] = ((i & (MAXLEN_ - 1)) == 0) ? 1 : 0;
            g_fin_seq[i] = 0;
        }
        if (tid < B_ * BEAM_) {
            g_alive_lp[tid]   = ((tid & (BEAM_ - 1)) == 0) ? 0.0f : -INFINITY;
            g_fin_scores[tid] = -NEG_INF_PEN;
            g_fin_flags[tid]  = 0;
        }
        if (tid < B_) g_batch_fin[tid] = 0;
        return;
    }
    int b = blk;                       // encoder pooling for batch b
    __shared__ int toks[S_];
    if (tid < S_) toks[tid] = src[b * S_ + tid];
    __syncthreads();
    float cnt = 0.0f;
    for (int s = 0; s < S_; s++) cnt += (toks[s] != 0) ? 1.0f : 0.0f;
    float denom = fmaxf(cnt, 1.0f);
    for (int d = tid; d < D_; d += blockDim.x) {
        float acc = 0.0f;
        for (int s = 0; s < S_; s++) {
            int tk = toks[s];
            if (tk != 0) acc += Esrc[(size_t)tk * D_ + d];
        }
        g_pooled[b * D_ + d] = __fdiv_rn(acc, denom);
    }
}

// ------------------------------ x prep + fp16x2 split -------------------------
__global__ void __launch_bounds__(512) k_prep(const float* __restrict__ Etgt, int t) {
    int r = blockIdx.x;
    int b = r >> 2;
    int tok = g_alive_seq[r * MAXLEN_ + t];
    int k = threadIdx.x;
    float v = Etgt[(size_t)tok * D_ + k] + g_pooled[b * D_ + k];
    __half h0 = __float2half_rn(v);
    float r1 = v - __half2float(h0);
    __half h1 = __float2half_rn(r1);
    int o = r * D_ + k;
    g_xsp16[o] = h0;
    g_xsp16[XSZ + o] = h1;
}

// ------------------------------ tensor-core GEMM + LSE + rz tail -------------
#define NCHUNK  16
#define STAGE_B 24576

__global__ void __launch_bounds__(256, 2) k_gemm(const float* __restrict__ bias) {
    extern __shared__ __align__(128) char smem[];
    __shared__ unsigned s_tk;
    const uint32_t base = smem_u32(smem);
    const int tid  = threadIdx.x;
    const int lane = tid & 31;
    const int wid  = tid >> 5;
    const int warp_m = wid >> 2;
    const int warp_n = wid & 3;
    const int nb = blockIdx.x * 128;

    static const int AI[3] = {0, 0, 1};
    static const int BI[3] = {0, 1, 0};

    float acc[2][4][4];
#pragma unroll
    for (int i = 0; i < 2; i++)
#pragma unroll
        for (int j = 0; j < 4; j++)
#pragma unroll
            for (int q = 0; q < 4; q++) acc[i][j][q] = 0.0f;

    const int arow = lane & 15;
    const int asel = lane >> 4;
    const int brow = (lane & 7) + 8 * ((lane >> 4) & 1);
    const int bsel = (lane >> 3) & 1;

    auto issue = [&](int c, int st) {
        const int k0 = c * 32;
        uint32_t sb = base + st * STAGE_B;
#pragma unroll
        for (int i = 0; i < 6; i++) {
            int seg = tid + i * 256;
            if (seg < 512) {
                int s = seg >> 8, rem = seg & 255;
                int r = rem >> 2, f = rem & 3;
                cp16(sb + (uint32_t)(s * 4096) + swz64(r, f),
                     g_xsp16 + s * XSZ + r * D_ + k0 + f * 8);
            } else {
                int q = seg - 512;
                int s = q >> 9, rem = q & 511;
                int n = rem >> 2, f = rem & 3;
                cp16(sb + 8192u + (uint32_t)(s * 8192) + swz64(n, f),
                     g_Wsp16 + (size_t)s * WSZ + (size_t)(nb + n) * D_ + k0 + f * 8);
            }
        }
    };

    issue(0, 0); CP_COMMIT();
    issue(1, 1); CP_COMMIT();

    for (int c = 0; c < NCHUNK; c++) {
        const int st = c % 3;
        CP_WAIT1();
        __syncthreads();
        if (c + 2 < NCHUNK) issue(c + 2, (c + 2) % 3);
        CP_COMMIT();

        const uint32_t As0 = base + st * STAGE_B;
        const uint32_t Bs0 = As0 + 8192u;
#pragma unroll
        for (int p = 0; p < 3; p++) {
            const uint32_t As = As0 + (uint32_t)(AI[p] * 4096);
            const uint32_t Bs = Bs0 + (uint32_t)(BI[p] * 8192);
#pragma unroll
            for (int ks = 0; ks < 2; ks++) {
                uint32_t af[2][4], bf[2][4];
#pragma unroll
                for (int i = 0; i < 2; i++) {
                    int r = warp_m * 32 + i * 16 + arow;
                    LDMX4(af[i][0], af[i][1], af[i][2], af[i][3],
                          As + swz64(r, ks * 2 + asel));
                }
#pragma unroll
                for (int jp = 0; jp < 2; jp++) {
                    int n = warp_n * 32 + jp * 16 + brow;
                    LDMX4(bf[jp][0], bf[jp][1], bf[jp][2], bf[jp][3],
                          Bs + swz64(n, ks * 2 + bsel));
                }
#pragma unroll
                for (int i = 0; i < 2; i++) {
#pragma unroll
                    for (int jn = 0; jn < 4; jn++) {
                        MMAF16(acc[i][jn], af[i], bf[jn >> 1][(jn & 1) * 2],
                               bf[jn >> 1][(jn & 1) * 2 + 1]);
                    }
                }
            }
        }
    }

    // ---- epilogue: store logits + per-(row, block) logsumexp partials ----
    CP_WAIT0();
    __syncthreads();
    float2* sl = reinterpret_cast<float2*>(smem);   // [64][4]

#pragma unroll
    for (int i = 0; i < 2; i++) {
        float lv0[8], lv1[8];
        int row0 = warp_m * 32 + i * 16 + (lane >> 2);
#pragma unroll
        for (int jn = 0; jn < 4; jn++) {
            int col = nb + warp_n * 32 + jn * 8 + (lane & 3) * 2;
            float2 bz = *reinterpret_cast<const float2*>(bias + col);
            float2 o0 = make_float2(acc[i][jn][0] + bz.x, acc[i][jn][1] + bz.y);
            float2 o1 = make_float2(acc[i][jn][2] + bz.x, acc[i][jn][3] + bz.y);
            *reinterpret_cast<float2*>(g_logits + (size_t)row0 * V_ + col) = o0;
            *reinterpret_cast<float2*>(g_logits + (size_t)(row0 + 8) * V_ + col) = o1;
            lv0[jn * 2] = o0.x; lv0[jn * 2 + 1] = o0.y;
            lv1[jn * 2] = o1.x; lv1[jn * 2 + 1] = o1.y;
        }
#pragma unroll
        for (int h = 0; h < 2; h++) {
            const float* lv = (h == 0) ? lv0 : lv1;
            float m = lv[0];
#pragma unroll
            for (int j = 1; j < 8; j++) m = fmaxf(m, lv[j]);
            float s = 0.0f;
#pragma unroll
            for (int j = 0; j < 8; j++) s += pexp(lv[j] - m);
#pragma unroll
            for (int off = 1; off <= 2; off <<= 1) {
                float om = __shfl_xor_sync(0xFFFFFFFFu, m, off);
                float os = __shfl_xor_sync(0xFFFFFFFFu, s, off);
                lse_mrg(m, s, om, os);
            }
            if ((lane & 3) == 0) {
                int rl = warp_m * 32 + i * 16 + h * 8 + (lane >> 2);
                sl[rl * 4 + warp_n] = make_float2(m, s);
            }
        }
    }
    __syncthreads();
    if (tid < 64) {
        float m = sl[tid * 4].x, s = sl[tid * 4].y;
#pragma unroll
        for (int j = 1; j < 4; j++)
            lse_mrg(m, s, sl[tid * 4 + j].x, sl[tid * 4 + j].y);
        g_pms2[tid * 256 + blockIdx.x] = make_float2(m, s);
    }

    // ---- last-block tail: reduce partials -> per-row (rm, rz) ----
    __threadfence();
    __syncthreads();
    if (tid == 0) s_tk = atomicAdd(&g_cnt_gemm, 1u);
    __syncthreads();
    if (s_tk == NBLK - 1) {
        for (int row = wid * 8; row < wid * 8 + 8; row++) {
            float m = -INFINITY, s = 0.0f;
            for (int i = lane; i < NBLK; i += 32) {
                float2 p = g_pms2[row * 256 + i];
                lse_mrg(m, s, p.x, p.y);
            }
#pragma unroll
            for (int off = 16; off > 0; off >>= 1) {
                float om = __shfl_xor_sync(0xFFFFFFFFu, m, off);
                float os = __shfl_xor_sync(0xFFFFFFFFu, s, off);
                lse_mrg(m, s, om, os);
            }
            if (lane == 0) g_rmz[row] = make_float2(m, logf(s));
        }
        __syncthreads();
        if (tid == 0) g_cnt_gemm = 0;
    }
}

// ------------------------------ score: exact quarter top-8 -------------------
// grid 256 = 4 blocks/row; reads precomputed (rm, rz); warp-shuffle selection
// (1 barrier). No serial tail.
__global__ void __launch_bounds__(256) k_score(int t) {
    const int blk = blockIdx.x;
    const int r = blk >> 2, q = blk & 3;
    const int tid = threadIdx.x;
    const int lane = tid & 31;
    const int wid = tid >> 5;
    const float lpen = (float)(t + 1);

    __shared__ unsigned long long wk[8][8];

    float2 mz = g_rmz[r];
    const float rm = mz.x, rz = mz.y;
    const float al = g_alive_lp[r];
    const unsigned int idxBase = (unsigned int)((r & 3) * V_ + q * 8000);

    const float4* lrow = reinterpret_cast<const float4*>(g_logits + (size_t)r * V_ + q * 8000);
    unsigned long long loc[8];
#pragma unroll
    for (int i = 0; i < 8; i++) loc[i] = 0ull;

    for (int i = tid; i < 2000; i += 256) {
        float4 x = lrow[i];
        float xs[4] = {x.x, x.y, x.z, x.w};
#pragma unroll
        for (int c = 0; c < 4; c++) {
            float lp = (xs[c] - rm) - rz;
            float sc = __fdiv_rn(al + lp, lpen);
            unsigned int idx = idxBase + (unsigned int)(i * 4 + c);
            unsigned long long key = ((unsigned long long)ford(sc) << 32)
                                   | (unsigned long long)(0xFFFFFFFFu - idx);
            if (key > loc[7]) {
                loc[7] = key;
#pragma unroll
                for (int j = 7; j > 0; j--) {
                    if (loc[j] > loc[j - 1]) {
                        unsigned long long tmp = loc[j]; loc[j] = loc[j - 1]; loc[j - 1] = tmp;
                    }
                }
            }
        }
    }

    // per-warp top-8 (loc sorted descending; tournament extract)
#pragma unroll
    for (int sel = 0; sel < 8; sel++) {
        unsigned long long mx = loc[0];
#pragma unroll
        for (int off = 16; off > 0; off >>= 1)
            mx = umax64(mx, __shfl_xor_sync(0xFFFFFFFFu, mx, off));
        if (loc[0] == mx) {
#pragma unroll
            for (int j = 0; j < 7; j++) loc[j] = loc[j + 1];
            loc[7] = 0ull;
        }
        if (lane == 0) wk[wid][sel] = mx;
    }
    __syncthreads();
    if (wid == 0) {
        const unsigned long long* fw = &wk[0][0];
        unsigned long long a = fw[lane], b = fw[lane + 32];
#pragma unroll
        for (int sel = 0; sel < 8; sel++) {
            unsigned long long mm = umax64(a, b);
#pragma unroll
            for (int off = 16; off > 0; off >>= 1)
                mm = umax64(mm, __shfl_xor_sync(0xFFFFFFFFu, mm, off));
            if (a == mm) a = 0ull;
            else if (b == mm) b = 0ull;
            if (lane == 0) g_cand[r * 32 + q * 8 + sel] = mm;
        }
    }
}

// ------------------------------ beam bookkeeping (warp per batch) ------------
__global__ void __launch_bounds__(512) k_book(int t) {
    const int tid = threadIdx.x;
    const int lane = tid & 31;
    const int b = tid >> 5;
    const float lpen = (float)(t + 1);

    unsigned long long k4[4];
#pragma unroll
    for (int j = 0; j < 4; j++) k4[j] = g_cand[b * 128 + lane * 4 + j];

    float sc[8]; int id[8];
#pragma unroll
    for (int sel = 0; sel < 8; sel++) {
        unsigned long long mx = umax64(umax64(k4[0], k4[1]), umax64(k4[2], k4[3]));
#pragma unroll
        for (int off = 16; off > 0; off >>= 1)
            mx = umax64(mx, __shfl_xor_sync(0xFFFFFFFFu, mx, off));
        sc[sel] = finv((unsigned int)(mx >> 32));
        id[sel] = (int)(0xFFFFFFFFu - (unsigned int)mx);
#pragma unroll
        for (int j = 0; j < 4; j++)
            if (k4[j] == mx) k4[j] = 0ull;   // keys unique
    }

    int tok[8], bix[8], fin[8]; float tlp[8];
#pragma unroll
    for (int j = 0; j < 8; j++) {
        tok[j] = id[j] % V_;
        bix[j] = (t == 0) ? (j & 3) : (id[j] / V_);
        fin[j] = (tok[j] == 2);
        tlp[j] = sc[j] * lpen;
    }

    float curr[8];
#pragma unroll
    for (int j = 0; j < 8; j++) curr[j] = sc[j] + (fin[j] ? -NEG_INF_PEN : 0.0f);
    int aidx[4];
    {
        unsigned usedm = 0;
#pragma unroll
        for (int sel = 0; sel < 4; sel++) {
            int best = -1; float bv = 0.0f;
#pragma unroll
            for (int j = 0; j < 8; j++)
                if (!((usedm >> j) & 1) && (best < 0 || curr[j] > bv)) {
                    best = j; bv = curr[j];
                }
            usedm |= 1u << best; aidx[sel] = best;
        }
    }

    float bfp = g_batch_fin[b] ? -NEG_INF_PEN : 0.0f;
    float cs[12]; int cfl[12];
#pragma unroll
    for (int k = 0; k < 4; k++) {
        cs[k]  = g_fin_scores[b * BEAM_ + k];
        cfl[k] = g_fin_flags[b * BEAM_ + k];
    }
#pragma unroll
    for (int j = 0; j < 8; j++) {
        cs[4 + j]  = (sc[j] + (fin[j] ? 0.0f : -NEG_INF_PEN)) + bfp;
        cfl[4 + j] = fin[j];
    }
    int fidx[4];
    {
        unsigned usedm = 0;
#pragma unroll
        for (int sel = 0; sel < 4; sel++) {
            int best = -1; float bv = 0.0f;
#pragma unroll
            for (int j = 0; j < 12; j++)
                if (!((usedm >> j) & 1) && (best < 0 || cs[j] > bv)) {
                    best = j; bv = cs[j];
                }
            usedm |= 1u << best; fidx[sel] = best;
        }
    }

    if (lane < MAXLEN_) {
        int a_old[4], f_old[4];
#pragma unroll
        for (int k = 0; k < 4; k++) {
            a_old[k] = g_alive_seq[(b * BEAM_ + k) * MAXLEN_ + lane];
            f_old[k] = g_fin_seq[(b * BEAM_ + k) * MAXLEN_ + lane];
        }
        int a_new[4], f_new[4];
#pragma unroll
        for (int k = 0; k < 4; k++) {
            int aj = aidx[k];
            int v = a_old[bix[aj]];
            if (lane == t + 1) v = tok[aj];
            a_new[k] = v;

            int fj = fidx[k];
            int w;
            if (fj < 4) {
                w = f_old[fj];
            } else {
                w = a_old[bix[fj - 4]];
                if (lane == t + 1) w = tok[fj - 4];
            }
            f_new[k] = w;
        }
#pragma unroll
        for (int k = 0; k < 4; k++) {
            g_alive_seq[(b * BEAM_ + k) * MAXLEN_ + lane] = a_new[k];
            g_fin_seq[(b * BEAM_ + k) * MAXLEN_ + lane]   = f_new[k];
        }
    }

    if (lane == 0) {
        float nalp[4], nfsc[4]; int nffl[4];
#pragma unroll
        for (int k = 0; k < 4; k++) {
            nalp[k] = tlp[aidx[k]];
            nfsc[k] = cs[fidx[k]];
            nffl[k] = cfl[fidx[k]];
            g_alive_lp[b * BEAM_ + k]   = nalp[k];
            g_fin_scores[b * BEAM_ + k] = nfsc[k];
            g_fin_flags[b * BEAM_ + k]  = nffl[k];
        }
        float lb = __fdiv_rn(nalp[0], lpen);
        float lf = nfsc[0] * (nffl[0] ? 1.0f : 0.0f);
#pragma unroll
        for (int k = 1; k < 4; k++) lf = fminf(lf, nfsc[k] * (nffl[k] ? 1.0f : 0.0f));
        bool allf = nffl[0] && nffl[1] && nffl[2] && nffl[3];
        lf = lf + (allf ? 0.0f : -NEG_INF_PEN);
        if (lf >= lb) g_batch_fin[b] = 1;
    }
}

// ------------------------------ output ---------------------------------------
__global__ void k_out(int* __restrict__ out) {
    int i = threadIdx.x;
    if (i < B_ * MAXLEN_) {
        int b = i / MAXLEN_, l = i % MAXLEN_;
        out[i] = g_fin_seq[(b * BEAM_ + 0) * MAXLEN_ + l];
    }
}

// ------------------------------ launcher -------------------------------------
extern "C" void kernel_launch(void* const* d_in, const int* in_sizes, int n_in,
                              void* d_out, int out_size) {
    (void)in_sizes; (void)n_in; (void)out_size;
    const int*   src  = (const int*)d_in[0];
    const float* Esrc = (const float*)d_in[1];
    const float* Etgt = (const float*)d_in[2];
    const float* W    = (const float*)d_in[3];
    const float* bias = (const float*)d_in[4];

    static int s_attr_done = 0;
    if (!s_attr_done) {
        cudaFuncSetAttribute(k_gemm, cudaFuncAttributeMaxDynamicSharedMemorySize,
                             3 * STAGE_B);
        s_attr_done = 1;
    }

    // launch order: setup(1), prep(2), gemm(3), score(4) <- ncu capture slot
    k_setup<<<4017, 256>>>(src, Esrc, W);
    k_prep<<<NR_, 512>>>(Etgt, 0);

    for (int t = 0; t < MAXLEN_ - 1; t++) {
        k_gemm<<<NBLK, 256, 3 * STAGE_B>>>(bias);
        k_score<<<NR_ * 4, 256>>>(t);
        k_book<<<1, 512>>>(t);
        if (t + 1 < MAXLEN_ - 1) k_prep<<<NR_, 512>>>(Etgt, t + 1);
    }
    k_out<<<1, 256>>>((int*)d_out);
}

// round 14
// speedup vs baseline: 3.1269x; 2.4996x over previous
#include <cuda_runtime.h>
#include <cuda_fp16.h>
#include <math.h>
#include <stdint.h>

// ---------------------------------------------------------------------------
// Beam search generator: B=16, BEAM=4, MAX_LEN=16, VOCAB=32000, D=512, S=128
// R14: R11 baseline (fp16x2 mma.sync GEMM, 979us) + warp-shuffle top-8
// selection in score2. No device-scope fences, no single-block tails.
// ---------------------------------------------------------------------------

#define B_      16
#define BEAM_   4
#define MAXLEN_ 16
#define V_      32000
#define D_      512
#define S_      128
#define NR_     64
#define NEG_INF_PEN 1e9f

#define WSZ     (V_ * D_)
#define XSZ     (NR_ * D_)
#define NBLK    250                   // gemm grid

// ------------------------------ device state --------------------------------
static __device__ __align__(16) float g_pooled[B_ * D_];
static __device__ __align__(16) __half g_Wsp16[2 * WSZ];        // W splits, [s][n][k]
static __device__ __align__(16) __half g_xsp16[2 * XSZ];        // x splits, [s][r][k]
static __device__ __align__(16) float g_logits[(size_t)NR_ * V_];
static __device__ float g_alive_lp[B_ * BEAM_];
static __device__ int   g_alive_seq[B_ * BEAM_ * MAXLEN_];
static __device__ float g_fin_scores[B_ * BEAM_];
static __device__ int   g_fin_seq[B_ * BEAM_ * MAXLEN_];
static __device__ int   g_fin_flags[B_ * BEAM_];
static __device__ int   g_batch_fin[B_];
static __device__ __align__(16) float2 g_pms2[NR_ * 256];       // per-(row,block) LSE partials
static __device__ unsigned long long g_cand[NR_ * 32];          // 4 quarters x 8 keys

// ------------------------------ generic helpers ------------------------------
__device__ __forceinline__ unsigned int ford(float f) {
    unsigned int u = __float_as_uint(f);
    return (u & 0x80000000u) ? ~u : (u | 0x80000000u);
}
__device__ __forceinline__ float finv(unsigned int u) {
    return __uint_as_float((u & 0x80000000u) ? (u ^ 0x80000000u) : ~u);
}
__device__ __forceinline__ unsigned long long umax64(unsigned long long a, unsigned long long b) {
    return a > b ? a : b;
}
// exp(u) for u in [-0.25, 0] on the FMA pipe; rel err < 2e-8. MUFU fallback else.
__device__ __forceinline__ float pexp(float u) {
    if (u < -0.25f) return __expf(u);
    float p = fmaf(u, 1.0f / 720.0f, 1.0f / 120.0f);
    p = fmaf(u, p, 1.0f / 24.0f);
    p = fmaf(u, p, 1.0f / 6.0f);
    p = fmaf(u, p, 0.5f);
    p = fmaf(u, p, 1.0f);
    p = fmaf(u, p, 1.0f);
    return p;
}
// online logsumexp pair merge (symmetric)
__device__ __forceinline__ void lse_mrg(float& m1, float& s1, float m2, float s2) {
    if (m2 > m1) { s1 = s1 * pexp(m1 - m2) + s2; m1 = m2; }
    else         { s1 += s2 * pexp(m2 - m1); }
}

// ------------------------------ PTX helpers (sm_80 baseline) -----------------
__device__ __forceinline__ uint32_t smem_u32(const void* p) {
    uint32_t a;
    asm("{ .reg .u64 t; cvta.to.shared.u64 t, %1; cvt.u32.u64 %0, t; }" : "=r"(a) : "l"(p));
    return a;
}
__device__ __forceinline__ void cp16(uint32_t dst, const void* src) {
    asm volatile("{ .reg .u64 g; cvta.to.global.u64 g, %1;\n\t"
                 "cp.async.cg.shared.global [%0], [g], 16; }"
                 :: "r"(dst), "l"(src) : "memory");
}
#define CP_COMMIT() asm volatile("cp.async.commit_group;" ::: "memory")
#define CP_WAIT1()  asm volatile("cp.async.wait_group 1;" ::: "memory")
#define CP_WAIT0()  asm volatile("cp.async.wait_group 0;" ::: "memory")

#define LDMX4(r0, r1, r2, r3, addr) \
    asm volatile("ldmatrix.sync.aligned.m8n8.x4.shared.b16 {%0,%1,%2,%3}, [%4];" \
                 : "=r"(r0), "=r"(r1), "=r"(r2), "=r"(r3) : "r"(addr))

#define MMAF16(d, a, b0r, b1r) \
    asm volatile("mma.sync.aligned.m16n8k16.row.col.f32.f16.f16.f32 " \
                 "{%0,%1,%2,%3}, {%4,%5,%6,%7}, {%8,%9}, {%0,%1,%2,%3};" \
                 : "+f"((d)[0]), "+f"((d)[1]), "+f"((d)[2]), "+f"((d)[3]) \
                 : "r"((a)[0]), "r"((a)[1]), "r"((a)[2]), "r"((a)[3]), \
                   "r"(b0r), "r"(b1r))

// SW64 swizzle for 64-byte rows: r = row, f = 16B-granule index (0..3)
__device__ __forceinline__ uint32_t swz64(int r, int f) {
    return (uint32_t)(r * 64 + ((f * 16) ^ ((r & 6) * 8)));
}

// ------------------------------ fused setup: wprep + init + pooling ----------
__global__ void __launch_bounds__(256) k_setup(const int* __restrict__ src,
                                               const float* __restrict__ Esrc,
                                               const float* __restrict__ W) {
    int tid = threadIdx.x;
    if (blockIdx.x < 4000) {           // W split (fp16x2) + transpose
        int ktile = blockIdx.x & 7;
        int ntile = blockIdx.x >> 3;
        int k0 = ktile * 64, n0 = ntile * 64;
        __shared__ float tile[64][65];
        for (int i = tid; i < 4096; i += 256) {
            int kk = i >> 6, nn = i & 63;
            tile[kk][nn] = W[(size_t)(k0 + kk) * V_ + n0 + nn];
        }
        __syncthreads();
        for (int i = tid; i < 4096; i += 256) {
            int nn = i >> 6, kk = i & 63;
            float v = tile[kk][nn];
            __half h0 = __float2half_rn(v);
            float r1 = v - __half2float(h0);
            __half h1 = __float2half_rn(r1);
            size_t o = (size_t)(n0 + nn) * D_ + k0 + kk;
            g_Wsp16[o] = h0;
            g_Wsp16[WSZ + o] = h1;
        }
        return;
    }
    int blk = blockIdx.x - 4000;
    if (blk == 16) {                   // state init
        for (int i = tid; i < 1024; i += 256) {
            g_alive_seq[i] = ((i & (MAXLEN_ - 1)) == 0) ? 1 : 0;
            g_fin_seq[i] = 0;
        }
        if (tid < B_ * BEAM_) {
            g_alive_lp[tid]   = ((tid & (BEAM_ - 1)) == 0) ? 0.0f : -INFINITY;
            g_fin_scores[tid] = -NEG_INF_PEN;
            g_fin_flags[tid]  = 0;
        }
        if (tid < B_) g_batch_fin[tid] = 0;
        return;
    }
    int b = blk;                       // encoder pooling for batch b
    __shared__ int toks[S_];
    if (tid < S_) toks[tid] = src[b * S_ + tid];
    __syncthreads();
    float cnt = 0.0f;
    for (int s = 0; s < S_; s++) cnt += (toks[s] != 0) ? 1.0f : 0.0f;
    float denom = fmaxf(cnt, 1.0f);
    for (int d = tid; d < D_; d += blockDim.x) {
        float acc = 0.0f;
        for (int s = 0; s < S_; s++) {
            int tk = toks[s];
            if (tk != 0) acc += Esrc[(size_t)tk * D_ + d];
        }
        g_pooled[b * D_ + d] = __fdiv_rn(acc, denom);
    }
}

// ------------------------------ x prep + fp16x2 split -------------------------
__global__ void __launch_bounds__(512) k_prep(const float* __restrict__ Etgt, int t) {
    int r = blockIdx.x;
    int b = r >> 2;
    int tok = g_alive_seq[r * MAXLEN_ + t];
    int k = threadIdx.x;
    float v = Etgt[(size_t)tok * D_ + k] + g_pooled[b * D_ + k];
    __half h0 = __float2half_rn(v);
    float r1 = v - __half2float(h0);
    __half h1 = __float2half_rn(r1);
    int o = r * D_ + k;
    g_xsp16[o] = h0;
    g_xsp16[XSZ + o] = h1;
}

// ------------------------------ tensor-core GEMM + fused LSE -----------------
// logits[64][32000] = x @ W + bias via fp16x2: 3 products (x0w0, x0w1, x1w0),
// K-chunk outer (16 chunks of 32), SW64 swizzle, 3-stage cp.async pipeline.
// Per-chunk smem 24KB. Epilogue: logits + per-(row,block) LSE partials.
// NO fence, NO tail (device-scope fences after bulk stores are poison).
#define NCHUNK  16
#define STAGE_B 24576

__global__ void __launch_bounds__(256, 2) k_gemm(const float* __restrict__ bias) {
    extern __shared__ __align__(128) char smem[];
    const uint32_t base = smem_u32(smem);
    const int tid  = threadIdx.x;
    const int lane = tid & 31;
    const int wid  = tid >> 5;
    const int warp_m = wid >> 2;
    const int warp_n = wid & 3;
    const int nb = blockIdx.x * 128;

    static const int AI[3] = {0, 0, 1};
    static const int BI[3] = {0, 1, 0};

    float acc[2][4][4];
#pragma unroll
    for (int i = 0; i < 2; i++)
#pragma unroll
        for (int j = 0; j < 4; j++)
#pragma unroll
            for (int q = 0; q < 4; q++) acc[i][j][q] = 0.0f;

    const int arow = lane & 15;
    const int asel = lane >> 4;
    const int brow = (lane & 7) + 8 * ((lane >> 4) & 1);
    const int bsel = (lane >> 3) & 1;

    auto issue = [&](int c, int st) {
        const int k0 = c * 32;
        uint32_t sb = base + st * STAGE_B;
#pragma unroll
        for (int i = 0; i < 6; i++) {
            int seg = tid + i * 256;
            if (seg < 512) {
                int s = seg >> 8, rem = seg & 255;
                int r = rem >> 2, f = rem & 3;
                cp16(sb + (uint32_t)(s * 4096) + swz64(r, f),
                     g_xsp16 + s * XSZ + r * D_ + k0 + f * 8);
            } else {
                int q = seg - 512;
                int s = q >> 9, rem = q & 511;
                int n = rem >> 2, f = rem & 3;
                cp16(sb + 8192u + (uint32_t)(s * 8192) + swz64(n, f),
                     g_Wsp16 + (size_t)s * WSZ + (size_t)(nb + n) * D_ + k0 + f * 8);
            }
        }
    };

    issue(0, 0); CP_COMMIT();
    issue(1, 1); CP_COMMIT();

    for (int c = 0; c < NCHUNK; c++) {
        const int st = c % 3;
        CP_WAIT1();
        __syncthreads();
        if (c + 2 < NCHUNK) issue(c + 2, (c + 2) % 3);
        CP_COMMIT();

        const uint32_t As0 = base + st * STAGE_B;
        const uint32_t Bs0 = As0 + 8192u;
#pragma unroll
        for (int p = 0; p < 3; p++) {
            const uint32_t As = As0 + (uint32_t)(AI[p] * 4096);
            const uint32_t Bs = Bs0 + (uint32_t)(BI[p] * 8192);
#pragma unroll
            for (int ks = 0; ks < 2; ks++) {
                uint32_t af[2][4], bf[2][4];
#pragma unroll
                for (int i = 0; i < 2; i++) {
                    int r = warp_m * 32 + i * 16 + arow;
                    LDMX4(af[i][0], af[i][1], af[i][2], af[i][3],
                          As + swz64(r, ks * 2 + asel));
                }
#pragma unroll
                for (int jp = 0; jp < 2; jp++) {
                    int n = warp_n * 32 + jp * 16 + brow;
                    LDMX4(bf[jp][0], bf[jp][1], bf[jp][2], bf[jp][3],
                          Bs + swz64(n, ks * 2 + bsel));
                }
#pragma unroll
                for (int i = 0; i < 2; i++) {
#pragma unroll
                    for (int jn = 0; jn < 4; jn++) {
                        MMAF16(acc[i][jn], af[i], bf[jn >> 1][(jn & 1) * 2],
                               bf[jn >> 1][(jn & 1) * 2 + 1]);
                    }
                }
            }
        }
    }

    // ---- epilogue: store logits + per-(row, block) logsumexp partials ----
    CP_WAIT0();
    __syncthreads();
    float2* sl = reinterpret_cast<float2*>(smem);   // [64][4]

#pragma unroll
    for (int i = 0; i < 2; i++) {
        float lv0[8], lv1[8];
        int row0 = warp_m * 32 + i * 16 + (lane >> 2);
#pragma unroll
        for (int jn = 0; jn < 4; jn++) {
            int col = nb + warp_n * 32 + jn * 8 + (lane & 3) * 2;
            float2 bz = *reinterpret_cast<const float2*>(bias + col);
            float2 o0 = make_float2(acc[i][jn][0] + bz.x, acc[i][jn][1] + bz.y);
            float2 o1 = make_float2(acc[i][jn][2] + bz.x, acc[i][jn][3] + bz.y);
            *reinterpret_cast<float2*>(g_logits + (size_t)row0 * V_ + col) = o0;
            *reinterpret_cast<float2*>(g_logits + (size_t)(row0 + 8) * V_ + col) = o1;
            lv0[jn * 2] = o0.x; lv0[jn * 2 + 1] = o0.y;
            lv1[jn * 2] = o1.x; lv1[jn * 2 + 1] = o1.y;
        }
#pragma unroll
        for (int h = 0; h < 2; h++) {
            const float* lv = (h == 0) ? lv0 : lv1;
            float m = lv[0];
#pragma unroll
            for (int j = 1; j < 8; j++) m = fmaxf(m, lv[j]);
            float s = 0.0f;
#pragma unroll
            for (int j = 0; j < 8; j++) s += pexp(lv[j] - m);
#pragma unroll
            for (int off = 1; off <= 2; off <<= 1) {
                float om = __shfl_xor_sync(0xFFFFFFFFu, m, off);
                float os = __shfl_xor_sync(0xFFFFFFFFu, s, off);
                lse_mrg(m, s, om, os);
            }
            if ((lane & 3) == 0) {
                int rl = warp_m * 32 + i * 16 + h * 8 + (lane >> 2);
                sl[rl * 4 + warp_n] = make_float2(m, s);
            }
        }
    }
    __syncthreads();
    if (tid < 64) {
        float m = sl[tid * 4].x, s = sl[tid * 4].y;
#pragma unroll
        for (int j = 1; j < 4; j++)
            lse_mrg(m, s, sl[tid * 4 + j].x, sl[tid * 4 + j].y);
        g_pms2[tid * 256 + blockIdx.x] = make_float2(m, s);
    }
}

// ------------------------------ score pass 2: exact quarter top-8 ------------
// grid 256 = 4 blocks/row; rebuilds (rm, rz) from 250 block partials via a
// fixed deterministic smem tree, then scans its 8000-elem quarter for top-8
// under key (ford(score)<<32 | ~flatidx). Warp-shuffle selection (1 barrier).
__global__ void __launch_bounds__(256) k_score2(int t) {
    const int blk = blockIdx.x;
    const int r = blk >> 2, q = blk & 3;
    const int tid = threadIdx.x;
    const int lane = tid & 31;
    const int wid = tid >> 5;

    __shared__ float2 smg[256];
    float2 pp = (tid < NBLK) ? g_pms2[r * 256 + tid] : make_float2(-INFINITY, 0.0f);
    smg[tid] = pp;
    __syncthreads();
    for (int off = 128; off > 0; off >>= 1) {
        if (tid < off) {
            float m = smg[tid].x, s = smg[tid].y;
            lse_mrg(m, s, smg[tid + off].x, smg[tid + off].y);
            smg[tid] = make_float2(m, s);
        }
        __syncthreads();
    }
    const float rm = smg[0].x;
    const float rz = logf(smg[0].y);
    const float al = g_alive_lp[r];
    const float lpen = (float)(t + 1);
    const unsigned int idxBase = (unsigned int)((r & 3) * V_ + q * 8000);

    const float4* lrow = reinterpret_cast<const float4*>(g_logits + (size_t)r * V_ + q * 8000);
    unsigned long long loc[8];
#pragma unroll
    for (int i = 0; i < 8; i++) loc[i] = 0ull;

    for (int i = tid; i < 2000; i += 256) {
        float4 x = lrow[i];
        float xs[4] = {x.x, x.y, x.z, x.w};
#pragma unroll
        for (int c = 0; c < 4; c++) {
            float lp = (xs[c] - rm) - rz;
            float sc = __fdiv_rn(al + lp, lpen);
            unsigned int idx = idxBase + (unsigned int)(i * 4 + c);
            unsigned long long key = ((unsigned long long)ford(sc) << 32)
                                   | (unsigned long long)(0xFFFFFFFFu - idx);
            if (key > loc[7]) {
                loc[7] = key;
#pragma unroll
                for (int j = 7; j > 0; j--) {
                    if (loc[j] > loc[j - 1]) {
                        unsigned long long tmp = loc[j]; loc[j] = loc[j - 1]; loc[j - 1] = tmp;
                    }
                }
            }
        }
    }

    // per-warp top-8 (loc sorted descending; tournament extract), then warp 0
    // merges the 64 warp-candidates. Keys unique -> selection order exact.
    __shared__ unsigned long long wk[8][8];
#pragma unroll
    for (int sel = 0; sel < 8; sel++) {
        unsigned long long mx = loc[0];
#pragma unroll
        for (int off = 16; off > 0; off >>= 1)
            mx = umax64(mx, __shfl_xor_sync(0xFFFFFFFFu, mx, off));
        if (loc[0] == mx) {
#pragma unroll
            for (int j = 0; j < 7; j++) loc[j] = loc[j + 1];
            loc[7] = 0ull;
        }
        if (lane == 0) wk[wid][sel] = mx;
    }
    __syncthreads();
    if (wid == 0) {
        const unsigned long long* fw = &wk[0][0];
        unsigned long long a = fw[lane], b = fw[lane + 32];
#pragma unroll
        for (int sel = 0; sel < 8; sel++) {
            unsigned long long mm = umax64(a, b);
#pragma unroll
            for (int off = 16; off > 0; off >>= 1)
                mm = umax64(mm, __shfl_xor_sync(0xFFFFFFFFu, mm, off));
            if (a == mm) a = 0ull;
            else if (b == mm) b = 0ull;
            if (lane == 0) g_cand[r * 32 + q * 8 + sel] = mm;
        }
    }
}

// ------------------------------ beam bookkeeping (warp per batch) ------------
__global__ void __launch_bounds__(512) k_book(int t) {
    const int tid = threadIdx.x;
    const int lane = tid & 31;
    const int b = tid >> 5;
    const float lpen = (float)(t + 1);

    unsigned long long k4[4];
#pragma unroll
    for (int j = 0; j < 4; j++) k4[j] = g_cand[b * 128 + lane * 4 + j];

    float sc[8]; int id[8];
#pragma unroll
    for (int sel = 0; sel < 8; sel++) {
        unsigned long long mx = umax64(umax64(k4[0], k4[1]), umax64(k4[2], k4[3]));
#pragma unroll
        for (int off = 16; off > 0; off >>= 1)
            mx = umax64(mx, __shfl_xor_sync(0xFFFFFFFFu, mx, off));
        sc[sel] = finv((unsigned int)(mx >> 32));
        id[sel] = (int)(0xFFFFFFFFu - (unsigned int)mx);
#pragma unroll
        for (int j = 0; j < 4; j++)
            if (k4[j] == mx) k4[j] = 0ull;   // keys unique
    }

    int tok[8], bix[8], fin[8]; float tlp[8];
#pragma unroll
    for (int j = 0; j < 8; j++) {
        tok[j] = id[j] % V_;
        bix[j] = (t == 0) ? (j & 3) : (id[j] / V_);
        fin[j] = (tok[j] == 2);
        tlp[j] = sc[j] * lpen;
    }

    float curr[8];
#pragma unroll
    for (int j = 0; j < 8; j++) curr[j] = sc[j] + (fin[j] ? -NEG_INF_PEN : 0.0f);
    int aidx[4];
    {
        unsigned usedm = 0;
#pragma unroll
        for (int sel = 0; sel < 4; sel++) {
            int best = -1; float bv = 0.0f;
#pragma unroll
            for (int j = 0; j < 8; j++)
                if (!((usedm >> j) & 1) && (best < 0 || curr[j] > bv)) {
                    best = j; bv = curr[j];
                }
            usedm |= 1u << best; aidx[sel] = best;
        }
    }

    float bfp = g_batch_fin[b] ? -NEG_INF_PEN : 0.0f;
    float cs[12]; int cfl[12];
#pragma unroll
    for (int k = 0; k < 4; k++) {
        cs[k]  = g_fin_scores[b * BEAM_ + k];
        cfl[k] = g_fin_flags[b * BEAM_ + k];
    }
#pragma unroll
    for (int j = 0; j < 8; j++) {
        cs[4 + j]  = (sc[j] + (fin[j] ? 0.0f : -NEG_INF_PEN)) + bfp;
        cfl[4 + j] = fin[j];
    }
    int fidx[4];
    {
        unsigned usedm = 0;
#pragma unroll
        for (int sel = 0; sel < 4; sel++) {
            int best = -1; float bv = 0.0f;
#pragma unroll
            for (int j = 0; j < 12; j++)
                if (!((usedm >> j) & 1) && (best < 0 || cs[j] > bv)) {
                    best = j; bv = cs[j];
                }
            usedm |= 1u << best; fidx[sel] = best;
        }
    }

    if (lane < MAXLEN_) {
        int a_old[4], f_old[4];
#pragma unroll
        for (int k = 0; k < 4; k++) {
            a_old[k] = g_alive_seq[(b * BEAM_ + k) * MAXLEN_ + lane];
            f_old[k] = g_fin_seq[(b * BEAM_ + k) * MAXLEN_ + lane];
        }
        int a_new[4], f_new[4];
#pragma unroll
        for (int k = 0; k < 4; k++) {
            int aj = aidx[k];
            int v = a_old[bix[aj]];
            if (lane == t + 1) v = tok[aj];
            a_new[k] = v;

            int fj = fidx[k];
            int w;
            if (fj < 4) {
                w = f_old[fj];
            } else {
                w = a_old[bix[fj - 4]];
                if (lane == t + 1) w = tok[fj - 4];
            }
            f_new[k] = w;
        }
#pragma unroll
        for (int k = 0; k < 4; k++) {
            g_alive_seq[(b * BEAM_ + k) * MAXLEN_ + lane] = a_new[k];
            g_fin_seq[(b * BEAM_ + k) * MAXLEN_ + lane]   = f_new[k];
        }
    }

    if (lane == 0) {
        float nalp[4], nfsc[4]; int nffl[4];
#pragma unroll
        for (int k = 0; k < 4; k++) {
            nalp[k] = tlp[aidx[k]];
            nfsc[k] = cs[fidx[k]];
            nffl[k] = cfl[fidx[k]];
            g_alive_lp[b * BEAM_ + k]   = nalp[k];
            g_fin_scores[b * BEAM_ + k] = nfsc[k];
            g_fin_flags[b * BEAM_ + k]  = nffl[k];
        }
        float lb = __fdiv_rn(nalp[0], lpen);
        float lf = nfsc[0] * (nffl[0] ? 1.0f : 0.0f);
#pragma unroll
        for (int k = 1; k < 4; k++) lf = fminf(lf, nfsc[k] * (nffl[k] ? 1.0f : 0.0f));
        bool allf = nffl[0] && nffl[1] && nffl[2] && nffl[3];
        lf = lf + (allf ? 0.0f : -NEG_INF_PEN);
        if (lf >= lb) g_batch_fin[b] = 1;
    }
}

// ------------------------------ output ---------------------------------------
__global__ void k_out(int* __restrict__ out) {
    int i = threadIdx.x;
    if (i < B_ * MAXLEN_) {
        int b = i / MAXLEN_, l = i % MAXLEN_;
        out[i] = g_fin_seq[(b * BEAM_ + 0) * MAXLEN_ + l];
    }
}

// ------------------------------ launcher -------------------------------------
extern "C" void kernel_launch(void* const* d_in, const int* in_sizes, int n_in,
                              void* d_out, int out_size) {
    (void)in_sizes; (void)n_in; (void)out_size;
    const int*   src  = (const int*)d_in[0];
    const float* Esrc = (const float*)d_in[1];
    const float* Etgt = (const float*)d_in[2];
    const float* W    = (const float*)d_in[3];
    const float* bias = (const float*)d_in[4];

    static int s_attr_done = 0;
    if (!s_attr_done) {
        cudaFuncSetAttribute(k_gemm, cudaFuncAttributeMaxDynamicSharedMemorySize,
                             3 * STAGE_B);
        s_attr_done = 1;
    }

    // launch order: setup(1), prep(2), gemm(3), score2(4) <- ncu capture slot
    k_setup<<<4017, 256>>>(src, Esrc, W);
    k_prep<<<NR_, 512>>>(Etgt, 0);

    for (int t = 0; t < MAXLEN_ - 1; t++) {
        k_gemm<<<NBLK, 256, 3 * STAGE_B>>>(bias);
        k_score2<<<NR_ * 4, 256>>>(t);
        k_book<<<1, 512>>>(t);
        if (t + 1 < MAXLEN_ - 1) k_prep<<<NR_, 512>>>(Etgt, t + 1);
    }
    k_out<<<1, 256>>>((int*)d_out);
}